// round 15
// baseline (speedup 1.0000x reference)
#include <cuda_runtime.h>
#include <cuda_fp16.h>
#include <cstdint>

// Fused MoE router gate — warp-autonomous mma.sync edition.
//   phase 1: fp16x3 split GEMM on legacy HMMA (mma.sync.m16n8k16.f16),
//            warp = m32 x n64 tile, operands loaded per-lane DIRECTLY from
//            global (W pre-split fp16 hi/lo in device globals; A split in
//            registers). No smem, no __syncthreads in the mainloop.
//   phase 2: softmax -> probs; top-9 ambiguity gate (tau=2e-4, validated R7)
//            -> emit approx top-8, or queue + bit-exact R1-replica (R7 code).

#define NE     64
#define TPB    64          // 2 warps per CTA
#define MT_CTA 64          // tokens per CTA (32 per warp)
#define NCAND  9
#define TAU    2e-4f

#define SCALE_A 256.0f
#define SCALE_B 1024.0f
#define INV_SCALE (1.0f / (SCALE_A * SCALE_B))   // 2^-18

__device__ __half g_Wh[NE * 2048];
__device__ __half g_Wl[NE * 2048];

#define MMA16816(C, a0, a1, a2, a3, b0, b1)                                  \
    asm volatile("mma.sync.aligned.m16n8k16.row.col.f32.f16.f16.f32 "        \
                 "{%0,%1,%2,%3}, {%4,%5,%6,%7}, {%8,%9}, {%0,%1,%2,%3};"     \
                 : "+f"((C)[0]), "+f"((C)[1]), "+f"((C)[2]), "+f"((C)[3])    \
                 : "r"(a0), "r"(a1), "r"(a2), "r"(a3), "r"(b0), "r"(b1))

__device__ __forceinline__ void split4(float4 v, float sc, uint2& hi, uint2& lo) {
    const float x0 = v.x * sc, x1 = v.y * sc, x2 = v.z * sc, x3 = v.w * sc;
    const __half h0 = __float2half_rn(x0);
    const __half h1 = __float2half_rn(x1);
    const __half h2 = __float2half_rn(x2);
    const __half h3 = __float2half_rn(x3);
    const __half l0 = __float2half_rn(x0 - __half2float(h0));
    const __half l1 = __float2half_rn(x1 - __half2float(h1));
    const __half l2 = __float2half_rn(x2 - __half2float(h2));
    const __half l3 = __float2half_rn(x3 - __half2float(h3));
    __half2 a{h0, h1}, b{h2, h3}, c{l0, l1}, d{l2, l3};
    hi.x = *(uint32_t*)&a; hi.y = *(uint32_t*)&b;
    lo.x = *(uint32_t*)&c; lo.y = *(uint32_t*)&d;
}

// prep: split W*SCALE_B into fp16 hi/lo once (identical formula as in-loop)
__global__ void split_w_kernel(const float* __restrict__ W, int n4)
{
    const int i = blockIdx.x * blockDim.x + threadIdx.x;
    if (i < n4) {
        uint2 hi, lo;
        split4(((const float4*)W)[i], SCALE_B, hi, lo);
        *(uint2*)&g_Wh[i * 4] = hi;
        *(uint2*)&g_Wl[i * 4] = lo;
    }
}

__device__ __forceinline__ void split2(float2 v, uint32_t& hi, uint32_t& lo) {
    const float x0 = v.x * SCALE_A, x1 = v.y * SCALE_A;
    const __half2 h = __floats2half2_rn(x0, x1);
    const float2 hf = __half22float2(h);
    const __half2 l = __floats2half2_rn(x0 - hf.x, x1 - hf.y);
    hi = *(const uint32_t*)&h;
    lo = *(const uint32_t*)&l;
}

__global__ __launch_bounds__(TPB)
void router_wmma(const float* __restrict__ H,
                 const float* __restrict__ W,
                 const float* __restrict__ cal_scale,
                 const float* __restrict__ cal_bias,
                 float* __restrict__ out_probs,
                 float* __restrict__ out_w,
                 float* __restrict__ out_idx,
                 int T, int D)
{
    __shared__ union { float Lg[MT_CTA][NE + 1]; float wpool[2][1056]; } sm;
    __shared__ int queue[MT_CTA];
    __shared__ int qcount;

    const int tid  = threadIdx.x;
    const int lane = tid & 31;
    const int warp = tid >> 5;               // 0..1
    const int qr   = lane >> 2;              // 0..7
    const int qc2  = (lane & 3) * 2;         // 0,2,4,6

    if (tid == 0) qcount = 0;

    const int wm = blockIdx.x * MT_CTA + warp * 32;   // warp's global token base

    // per-lane A row pointers (clamped; T divisible by 64 in practice)
    const float* ap[2][2];
    #pragma unroll
    for (int mi = 0; mi < 2; ++mi) {
        const int r0 = min(wm + mi * 16 + qr,     T - 1);
        const int r1 = min(wm + mi * 16 + qr + 8, T - 1);
        ap[mi][0] = H + (size_t)r0 * D;
        ap[mi][1] = H + (size_t)r1 * D;
    }

    float acc[2][8][4];
    #pragma unroll
    for (int mi = 0; mi < 2; ++mi)
        #pragma unroll
        for (int ni = 0; ni < 8; ++ni)
            #pragma unroll
            for (int c = 0; c < 4; ++c) acc[mi][ni][c] = 0.f;

    // B per-lane base offset (expert qr, col qc2)
    const uint32_t wb = (uint32_t)qr * 2048u + (uint32_t)qc2;

    // prefetch step-0 A raw
    float2 pr[8];
    #pragma unroll
    for (int mi = 0; mi < 2; ++mi) {
        pr[mi * 4 + 0] = *(const float2*)(ap[mi][0] + qc2);
        pr[mi * 4 + 1] = *(const float2*)(ap[mi][1] + qc2);
        pr[mi * 4 + 2] = *(const float2*)(ap[mi][0] + 8 + qc2);
        pr[mi * 4 + 3] = *(const float2*)(ap[mi][1] + 8 + qc2);
    }

    const int KT = D / 16;                   // 128 k16 steps
    for (int kt = 0; kt < KT; ++kt) {
        const int kk = kt * 16;

        // convert current A raw -> hi/lo fragments
        uint32_t ah[2][4], al[2][4];
        #pragma unroll
        for (int mi = 0; mi < 2; ++mi)
            #pragma unroll
            for (int j = 0; j < 4; ++j)
                split2(pr[mi * 4 + j], ah[mi][j], al[mi][j]);

        // prefetch next step A raw
        if (kt + 1 < KT) {
            const int kn = kk + 16;
            #pragma unroll
            for (int mi = 0; mi < 2; ++mi) {
                pr[mi * 4 + 0] = *(const float2*)(ap[mi][0] + kn + qc2);
                pr[mi * 4 + 1] = *(const float2*)(ap[mi][1] + kn + qc2);
                pr[mi * 4 + 2] = *(const float2*)(ap[mi][0] + kn + 8 + qc2);
                pr[mi * 4 + 3] = *(const float2*)(ap[mi][1] + kn + 8 + qc2);
            }
        }

        // B fragments direct from pre-split globals (L1-resident) + MMAs
        const __half* bhp = g_Wh + wb + kk;
        const __half* blp = g_Wl + wb + kk;
        #pragma unroll
        for (int ni = 0; ni < 8; ++ni) {
            const uint32_t b0h = *(const uint32_t*)(bhp + (size_t)ni * 8 * 2048);
            const uint32_t b1h = *(const uint32_t*)(bhp + (size_t)ni * 8 * 2048 + 8);
            const uint32_t b0l = *(const uint32_t*)(blp + (size_t)ni * 8 * 2048);
            const uint32_t b1l = *(const uint32_t*)(blp + (size_t)ni * 8 * 2048 + 8);
            #pragma unroll
            for (int mi = 0; mi < 2; ++mi) {
                MMA16816(acc[mi][ni], ah[mi][0], ah[mi][1], ah[mi][2], ah[mi][3], b0h, b1h);
                MMA16816(acc[mi][ni], ah[mi][0], ah[mi][1], ah[mi][2], ah[mi][3], b0l, b1l);
                MMA16816(acc[mi][ni], al[mi][0], al[mi][1], al[mi][2], al[mi][3], b0h, b1h);
            }
        }
    }

    // ---------- epilogue: calibrate -> Lg (warp-local rows) ----------
    #pragma unroll
    for (int mi = 0; mi < 2; ++mi) {
        #pragma unroll
        for (int ni = 0; ni < 8; ++ni) {
            const int n0 = ni * 8 + qc2;
            const float s0 = __ldg(cal_scale + n0) * INV_SCALE;
            const float s1 = __ldg(cal_scale + n0 + 1) * INV_SCALE;
            const float bb0 = __ldg(cal_bias + n0), bb1 = __ldg(cal_bias + n0 + 1);
            const int lr = warp * 32 + mi * 16 + qr;
            sm.Lg[lr][n0]         = acc[mi][ni][0] * s0 + bb0;
            sm.Lg[lr][n0 + 1]     = acc[mi][ni][1] * s1 + bb1;
            sm.Lg[lr + 8][n0]     = acc[mi][ni][2] * s0 + bb0;
            sm.Lg[lr + 8][n0 + 1] = acc[mi][ni][3] * s1 + bb1;
        }
    }
    __syncthreads();                         // Lg complete; qcount visible

    // ---------- phase 2: softmax + gated top-8 (R7 math, warp-local rows) ----------
    for (int t = warp * 32; t < warp * 32 + 32; ++t) {
        const int tg = blockIdx.x * MT_CTA + t;
        if (tg >= T) break;

        const float v0 = sm.Lg[t][lane];
        const float v1 = sm.Lg[t][lane + 32];

        float mx = fmaxf(v0, v1);
        #pragma unroll
        for (int o = 16; o; o >>= 1)
            mx = fmaxf(mx, __shfl_xor_sync(0xffffffffu, mx, o));

        const float e0 = expf(v0 - mx);
        const float e1 = expf(v1 - mx);
        float s = e0 + e1;
        #pragma unroll
        for (int o = 16; o; o >>= 1)
            s += __shfl_xor_sync(0xffffffffu, s, o);

        const float inv = 1.0f / s;
        const float q0 = e0 * inv;
        const float q1 = e1 * inv;

        out_probs[(size_t)tg * NE + lane]      = q0;
        out_probs[(size_t)tg * NE + lane + 32] = q1;

        float p0 = q0, p1 = q1;
        float bvs[NCAND]; int cds[NCAND];
        #pragma unroll
        for (int r = 0; r < NCAND; ++r) {
            float bv; int bi;
            if (p0 >= p1) { bv = p0; bi = lane; }
            else          { bv = p1; bi = lane + 32; }
            #pragma unroll
            for (int o = 16; o; o >>= 1) {
                const float ov = __shfl_xor_sync(0xffffffffu, bv, o);
                const int   oi = __shfl_xor_sync(0xffffffffu, bi, o);
                if (ov > bv || (ov == bv && oi < bi)) { bv = ov; bi = oi; }
            }
            bvs[r] = bv; cds[r] = bi;
            if (bi == lane)           p0 = -1.0f;
            else if (bi == lane + 32) p1 = -1.0f;
        }

        bool amb = false;
        #pragma unroll
        for (int r = 0; r < 8; ++r)
            amb = amb || ((bvs[r] - bvs[r + 1]) < bvs[r] * TAU);

        if (!amb) {
            if (lane == 0) {
                #pragma unroll
                for (int r = 0; r < 8; ++r) {
                    out_w[(size_t)tg * 8 + r]   = bvs[r];
                    out_idx[(size_t)tg * 8 + r] = (float)cds[r];
                }
            }
        } else if (lane == 0) {
            const int q = atomicAdd(&qcount, 1);
            queue[q] = tg;
        }
    }
    __syncthreads();                         // phase2 done; wpool may reuse Lg

    // ====== replica pass: bit-exact R1 arithmetic on queued tokens (R7 verbatim) ======
    const int nq = qcount;
    float* Wa = sm.wpool[warp];              // [16][33]
    float* Wb = Wa + 528;                    // [16][33]
    const int rr = lane >> 2;                // row group 0..7
    const int ff = lane & 3;                 // float4 slot 0..3
    const int D4 = D / 4;

    for (int qi = warp; qi < nq; qi += 2) {
        const int tg = queue[qi];
        const float4* H4 = (const float4*)(H + (size_t)tg * D);
        const float4* W4 = (const float4*)W;

        float acc0 = 0.f, acc1 = 0.f;
        float4 pre[8];
        #pragma unroll
        for (int j = 0; j < 8; ++j)
            pre[j] = W4[(size_t)(rr + 8 * j) * D4 + ff];

        for (int kb = 0; kb < 128; ++kb) {   // 16 k per block, k ascending
            #pragma unroll
            for (int j = 0; j < 8; ++j) {
                const int e = rr + 8 * j;
                float* dst = (e < 32) ? (Wa + e) : (Wb + (e - 32));
                dst[(4 * ff + 0) * 33] = pre[j].x;
                dst[(4 * ff + 1) * 33] = pre[j].y;
                dst[(4 * ff + 2) * 33] = pre[j].z;
                dst[(4 * ff + 3) * 33] = pre[j].w;
            }
            __syncwarp();
            if (kb + 1 < 128) {
                #pragma unroll
                for (int j = 0; j < 8; ++j)
                    pre[j] = W4[(size_t)(rr + 8 * j) * D4 + (kb + 1) * 4 + ff];
            }
            #pragma unroll
            for (int q4 = 0; q4 < 4; ++q4) {
                const float4 h = H4[kb * 4 + q4];
                const int k0 = q4 * 4;
                acc0 = fmaf(h.x, Wa[(k0 + 0) * 33 + lane], acc0);
                acc0 = fmaf(h.y, Wa[(k0 + 1) * 33 + lane], acc0);
                acc0 = fmaf(h.z, Wa[(k0 + 2) * 33 + lane], acc0);
                acc0 = fmaf(h.w, Wa[(k0 + 3) * 33 + lane], acc0);
                acc1 = fmaf(h.x, Wb[(k0 + 0) * 33 + lane], acc1);
                acc1 = fmaf(h.y, Wb[(k0 + 1) * 33 + lane], acc1);
                acc1 = fmaf(h.z, Wb[(k0 + 2) * 33 + lane], acc1);
                acc1 = fmaf(h.w, Wb[(k0 + 3) * 33 + lane], acc1);
            }
            __syncwarp();
        }

        const float v0 = acc0 * cal_scale[lane] + cal_bias[lane];
        const float v1 = acc1 * cal_scale[lane + 32] + cal_bias[lane + 32];

        float mx = fmaxf(v0, v1);
        #pragma unroll
        for (int o = 16; o; o >>= 1)
            mx = fmaxf(mx, __shfl_xor_sync(0xffffffffu, mx, o));

        const float e0 = expf(v0 - mx);
        const float e1 = expf(v1 - mx);
        float s = e0 + e1;
        #pragma unroll
        for (int o = 16; o; o >>= 1)
            s += __shfl_xor_sync(0xffffffffu, s, o);

        const float inv = 1.0f / s;
        float p0 = e0 * inv;
        float p1 = e1 * inv;

        #pragma unroll
        for (int r = 0; r < 8; ++r) {
            float bv; int bi;
            if (p0 >= p1) { bv = p0; bi = lane; }
            else          { bv = p1; bi = lane + 32; }
            #pragma unroll
            for (int o = 16; o; o >>= 1) {
                const float ov = __shfl_xor_sync(0xffffffffu, bv, o);
                const int   oi = __shfl_xor_sync(0xffffffffu, bi, o);
                if (ov > bv || (ov == bv && oi < bi)) { bv = ov; bi = oi; }
            }
            if (lane == 0) {
                out_w[(size_t)tg * 8 + r]   = bv;
                out_idx[(size_t)tg * 8 + r] = (float)bi;
            }
            if (bi == lane)           p0 = -1.0f;
            else if (bi == lane + 32) p1 = -1.0f;
        }
    }
}

extern "C" void kernel_launch(void* const* d_in, const int* in_sizes, int n_in,
                              void* d_out, int out_size)
{
    const float* H  = (const float*)d_in[0];
    const float* W  = (const float*)d_in[1];
    const float* cs = (const float*)d_in[2];
    const float* cb = (const float*)d_in[3];

    const int E = in_sizes[2];
    const int D = in_sizes[1] / E;
    const int T = in_sizes[0] / D;

    float* out       = (float*)d_out;
    float* out_probs = out;
    float* out_w     = out + (size_t)T * E;
    float* out_idx   = out_w + (size_t)T * 8;

    const int n4 = (E * D) / 4;
    split_w_kernel<<<(n4 + 255) / 256, 256>>>(W, n4);

    const int grid = (T + MT_CTA - 1) / MT_CTA;   // 256
    router_wmma<<<grid, TPB>>>(H, W, cs, cb, out_probs, out_w, out_idx, T, D);
}

// round 16
// speedup vs baseline: 3.5237x; 3.5237x over previous
#include <cuda_runtime.h>
#include <cuda_bf16.h>

// Fused MoE router gate — pure fp32 FFMA, 8x8 thread tiles (R1 math exactly):
//   logits = (H[T,D] @ W[E,D]^T) * cal_scale + cal_bias
//   probs -> out[0:T*E]; top8 weights -> +T*8; top8 idx -> +T*8
// Per thread-k: 4 LDS.128 per 64 FMA (1 B/FMA = crossbar parity with 2.5x slack
// at the 128 FMA/cyc/SM fp32 rate). TPB=128 -> 4 warps = all 4 SMSPs busy.
// Every logit is a single sequential k-ascending fmaf chain with operands
// identical to the R1 kernel (passed: rel_err 1.08e-7, indices exact).

#define KC  16      // K chunk per stage
#define MT  128     // token tile per block
#define NE  64      // experts
#define TPB 128     // 4 warps; tx = tid&7 (n0=tx*8), ty = tid>>3 (m0=ty*8)

__global__ __launch_bounds__(TPB)
void router_ffma8(const float* __restrict__ H,
                  const float* __restrict__ W,
                  const float* __restrict__ cal_scale,
                  const float* __restrict__ cal_bias,
                  float* __restrict__ out_probs,
                  float* __restrict__ out_w,
                  float* __restrict__ out_idx,
                  int T, int D)
{
    __shared__ __align__(16) union {
        struct {
            float As[2][KC][MT + 4];   // [k][m] transposed, 132-float rows
            float Bs[2][KC][NE + 4];   // [k][e] transposed, 68-float rows
        } s;
        float Lg[MT][NE + 1];
    } sm;

    const int tid = threadIdx.x;
    const int tx  = tid & 7;           // n0 = tx*8
    const int ty  = tid >> 3;          // m0 = ty*8 (0..15)
    const int m_base = blockIdx.x * MT;

    // ---- loaders ----
    const int lrow = tid;              // A: one token row per thread (16 floats)
    const int brow = tid >> 1;         // B: expert row (8 floats)
    const int bk   = (tid & 1) * 8;

    const bool a_ok = (m_base + lrow) < T;
    const float* Ap = H + (size_t)(m_base + lrow) * D;
    const float* Bp = W + (size_t)brow * D + bk;

    const float4 z4 = make_float4(0.f, 0.f, 0.f, 0.f);
    float4 a_pf[4], b_pf[2];
    #pragma unroll
    for (int q = 0; q < 4; ++q) a_pf[q] = a_ok ? *(const float4*)(Ap + q * 4) : z4;
    #pragma unroll
    for (int j = 0; j < 2; ++j) b_pf[j] = *(const float4*)(Bp + j * 4);

    float acc[8][8];
    #pragma unroll
    for (int i = 0; i < 8; ++i)
        #pragma unroll
        for (int j = 0; j < 8; ++j) acc[i][j] = 0.f;

    const int KT = D / KC;             // 128 stages
    int buf = 0;
    for (int kt = 0; kt < KT; ++kt) {
        // ---- store prefetched stage (transposed) ----
        #pragma unroll
        for (int q = 0; q < 4; ++q) {
            sm.s.As[buf][q * 4 + 0][lrow] = a_pf[q].x;
            sm.s.As[buf][q * 4 + 1][lrow] = a_pf[q].y;
            sm.s.As[buf][q * 4 + 2][lrow] = a_pf[q].z;
            sm.s.As[buf][q * 4 + 3][lrow] = a_pf[q].w;
        }
        #pragma unroll
        for (int j = 0; j < 2; ++j) {
            sm.s.Bs[buf][bk + j * 4 + 0][brow] = b_pf[j].x;
            sm.s.Bs[buf][bk + j * 4 + 1][brow] = b_pf[j].y;
            sm.s.Bs[buf][bk + j * 4 + 2][brow] = b_pf[j].z;
            sm.s.Bs[buf][bk + j * 4 + 3][brow] = b_pf[j].w;
        }
        __syncthreads();

        // ---- prefetch next stage ----
        if (kt + 1 < KT) {
            const float* Apn = Ap + (size_t)(kt + 1) * KC;
            const float* Bpn = Bp + (size_t)(kt + 1) * KC;
            #pragma unroll
            for (int q = 0; q < 4; ++q) a_pf[q] = a_ok ? *(const float4*)(Apn + q * 4) : z4;
            #pragma unroll
            for (int j = 0; j < 2; ++j) b_pf[j] = *(const float4*)(Bpn + j * 4);
        }

        // ---- compute: 8x8 rank-1 updates, frag double-buffered over k ----
        float4 af[2][2], bf[2][2];
        af[0][0] = *(const float4*)&sm.s.As[buf][0][ty * 8];
        af[0][1] = *(const float4*)&sm.s.As[buf][0][ty * 8 + 4];
        bf[0][0] = *(const float4*)&sm.s.Bs[buf][0][tx * 8];
        bf[0][1] = *(const float4*)&sm.s.Bs[buf][0][tx * 8 + 4];
        #pragma unroll
        for (int k = 0; k < KC; ++k) {
            const int cur = k & 1, nxt = cur ^ 1;
            if (k + 1 < KC) {
                af[nxt][0] = *(const float4*)&sm.s.As[buf][k + 1][ty * 8];
                af[nxt][1] = *(const float4*)&sm.s.As[buf][k + 1][ty * 8 + 4];
                bf[nxt][0] = *(const float4*)&sm.s.Bs[buf][k + 1][tx * 8];
                bf[nxt][1] = *(const float4*)&sm.s.Bs[buf][k + 1][tx * 8 + 4];
            }
            const float a[8] = {af[cur][0].x, af[cur][0].y, af[cur][0].z, af[cur][0].w,
                                af[cur][1].x, af[cur][1].y, af[cur][1].z, af[cur][1].w};
            const float b[8] = {bf[cur][0].x, bf[cur][0].y, bf[cur][0].z, bf[cur][0].w,
                                bf[cur][1].x, bf[cur][1].y, bf[cur][1].z, bf[cur][1].w};
            #pragma unroll
            for (int i = 0; i < 8; ++i) {
                #pragma unroll
                for (int j = 0; j < 8; ++j)
                    acc[i][j] = fmaf(a[i], b[j], acc[i][j]);
            }
        }
        buf ^= 1;
    }

    // ---- calibrate -> Lg (smem union; sync before reuse) ----
    __syncthreads();
    #pragma unroll
    for (int j = 0; j < 8; ++j) {
        const int n = tx * 8 + j;
        const float s = cal_scale[n];
        const float b = cal_bias[n];
        #pragma unroll
        for (int i = 0; i < 8; ++i)
            sm.Lg[ty * 8 + i][n] = acc[i][j] * s + b;
    }
    __syncthreads();

    // ---- warp-per-token softmax + top-8 (R1 verbatim) ----
    const int warp = tid >> 5;
    const int lane = tid & 31;
    for (int t = warp; t < MT; t += (TPB / 32)) {
        const int tg = m_base + t;
        if (tg >= T) break;

        float v0 = sm.Lg[t][lane];
        float v1 = sm.Lg[t][lane + 32];

        float mx = fmaxf(v0, v1);
        #pragma unroll
        for (int o = 16; o; o >>= 1)
            mx = fmaxf(mx, __shfl_xor_sync(0xffffffffu, mx, o));

        float e0 = expf(v0 - mx);
        float e1 = expf(v1 - mx);
        float s = e0 + e1;
        #pragma unroll
        for (int o = 16; o; o >>= 1)
            s += __shfl_xor_sync(0xffffffffu, s, o);

        const float inv = 1.0f / s;
        float p0 = e0 * inv;
        float p1 = e1 * inv;

        out_probs[(size_t)tg * NE + lane]      = p0;
        out_probs[(size_t)tg * NE + lane + 32] = p1;

        #pragma unroll
        for (int r = 0; r < 8; ++r) {
            float bv; int bi;
            if (p0 >= p1) { bv = p0; bi = lane; }
            else          { bv = p1; bi = lane + 32; }
            #pragma unroll
            for (int o = 16; o; o >>= 1) {
                const float ov = __shfl_xor_sync(0xffffffffu, bv, o);
                const int   oi = __shfl_xor_sync(0xffffffffu, bi, o);
                if (ov > bv || (ov == bv && oi < bi)) { bv = ov; bi = oi; }
            }
            if (lane == 0) {
                out_w[(size_t)tg * 8 + r]   = bv;
                out_idx[(size_t)tg * 8 + r] = (float)bi;
            }
            if (bi == lane)           p0 = -1.0f;
            else if (bi == lane + 32) p1 = -1.0f;
        }
    }
}

extern "C" void kernel_launch(void* const* d_in, const int* in_sizes, int n_in,
                              void* d_out, int out_size)
{
    const float* H  = (const float*)d_in[0];   // hidden_states [B,S,D] fp32
    const float* W  = (const float*)d_in[1];   // router_weight [E,D]  fp32
    const float* cs = (const float*)d_in[2];   // cal_scale [E]
    const float* cb = (const float*)d_in[3];   // cal_bias  [E]

    const int E = in_sizes[2];                 // 64
    const int D = in_sizes[1] / E;             // 2048
    const int T = in_sizes[0] / D;             // 16384

    float* out       = (float*)d_out;
    float* out_probs = out;                    // [T, E]
    float* out_w     = out + (size_t)T * E;    // [T, 8]
    float* out_idx   = out_w + (size_t)T * 8;  // [T, 8]

    const int grid = (T + MT - 1) / MT;        // 128
    router_ffma8<<<grid, TPB>>>(H, W, cs, cb, out_probs, out_w, out_idx, T, D);
}